// round 17
// baseline (speedup 1.0000x reference)
#include <cuda_runtime.h>
#include <cuda.h>
#include <cuda_fp16.h>
#include <math.h>
#include <stdint.h>

#define BB   2
#define Lseq 2048
#define BL   4096      // B*L
#define Dd   2048
#define DCc  1024
#define NHh  16
#define DHh  128
#define DHRr 64
#define ATTN_SCALE 0.07216878364870322f
#define NX   2176      // fused down-proj width: [ckv 1024 | cq 1024 | kr 64 | lam 16 | pad 48]

// ======================= scratch =======================
__device__ float  g_tmp [BL * NX];
__device__ float  g_lam [BL * NHh];

// fp16 split planes (activations)
__device__ __half g_xh  [BL * Dd],   g_xl  [BL * Dd];
__device__ __half g_ckvh[BL * DCc],  g_ckvl[BL * DCc];
__device__ __half g_cqh [BL * DCc],  g_cql [BL * DCc];
__device__ __half g_preh[BL * Dd];
__device__ __half g_qch [BL * 4096];
__device__ __half g_qrh [BL * 2048];
__device__ __half g_krh [BL * DHRr];
__device__ __half g_kvh [BL * 4096];   // [kc 2048 | v 2048]
// fp16 split planes (transposed weights, [N][K])
__device__ __half g_tXh  [NX * Dd],     g_tXl  [NX * Dd];     // [DKV|DQ|KR|lw|pad0]
__device__ __half g_tUKVh[4096 * DCc];
__device__ __half g_tUQh [4096 * DCc];
__device__ __half g_tQRh [2048 * DCc];
__device__ __half g_tOUTh[Dd * Dd];

// ======================= helpers =======================
__device__ __forceinline__ uint32_t smem_u32(const void* p) {
    uint32_t a;
    asm("{ .reg .u64 t; cvta.to.shared.u64 t, %1; cvt.u32.u64 %0, t; }" : "=r"(a) : "l"(p));
    return a;
}
__device__ __forceinline__ void cp16(uint32_t dst, const void* src) {
    asm volatile("cp.async.cg.shared.global [%0], [%1], 16;" :: "r"(dst), "l"(src));
}
#define CP_COMMIT() asm volatile("cp.async.commit_group;" ::: "memory")
#define CP_WAIT0()  asm volatile("cp.async.wait_group 0;"  ::: "memory")

__device__ __forceinline__ void mma_f16(float c[4],
                                        uint32_t a0, uint32_t a1, uint32_t a2, uint32_t a3,
                                        uint32_t b0, uint32_t b1)
{
    asm volatile(
        "mma.sync.aligned.m16n8k16.row.col.f32.f16.f16.f32 "
        "{%0,%1,%2,%3}, {%4,%5,%6,%7}, {%8,%9}, {%0,%1,%2,%3};"
        : "+f"(c[0]), "+f"(c[1]), "+f"(c[2]), "+f"(c[3])
        : "r"(a0), "r"(a1), "r"(a2), "r"(a3), "r"(b0), "r"(b1));
}
// fp16-accumulator HMMA (lo-term correction path)
__device__ __forceinline__ void mma_h16(uint32_t c[2],
                                        uint32_t a0, uint32_t a1, uint32_t a2, uint32_t a3,
                                        uint32_t b0, uint32_t b1)
{
    asm volatile(
        "mma.sync.aligned.m16n8k16.row.col.f16.f16.f16.f16 "
        "{%0,%1}, {%2,%3,%4,%5}, {%6,%7}, {%0,%1};"
        : "+r"(c[0]), "+r"(c[1])
        : "r"(a0), "r"(a1), "r"(a2), "r"(a3), "r"(b0), "r"(b1));
}

__device__ __forceinline__ void split16(float v, __half& h, __half& l) {
    h = __float2half_rn(v);
    l = __float2half_rn(v - __half2float(h));
}

// ======================= transpose + split: in[R][C] -> hi/lo[C][R] =======================
__global__ void transpose32h(const float* __restrict__ in,
                             __half* __restrict__ oh, __half* __restrict__ ol, int R, int C)
{
    __shared__ float t[32][33];
    int bx = blockIdx.x * 32, by = blockIdx.y * 32;
    int x = bx + threadIdx.x;
    #pragma unroll
    for (int j = 0; j < 32; j += 8)
        t[threadIdx.y + j][threadIdx.x] = in[(size_t)(by + threadIdx.y + j) * C + x];
    __syncthreads();
    int ox = by + threadIdx.x;
    #pragma unroll
    for (int j = 0; j < 32; j += 8) {
        float v = t[threadIdx.x][threadIdx.y + j];
        size_t o = (size_t)(bx + threadIdx.y + j) * R + ox;
        if (ol) {
            __half h, l; split16(v, h, l);
            oh[o] = h; ol[o] = l;
        } else {
            oh[o] = __float2half_rn(v);
        }
    }
}

// W_lw [2048][16] -> rows 2112..2127 of tX planes
__global__ void lwT_kernel(const float* __restrict__ Wl,
                           __half* __restrict__ oh, __half* __restrict__ ol)
{
    int idx = blockIdx.x * 256 + threadIdx.x;   // 2048*16
    int k = idx >> 4, n = idx & 15;
    float v = Wl[idx];
    __half h, l; split16(v, h, l);
    size_t o = (size_t)(2112 + n) * Dd + k;
    oh[o] = h; ol[o] = l;
}

// ======================= elementwise split =======================
__global__ void split_kernel(const float* __restrict__ in,
                             __half* __restrict__ oh, __half* __restrict__ ol)
{
    int idx = blockIdx.x * 256 + threadIdx.x;
    float v = in[idx];
    __half h, l; split16(v, h, l);
    oh[idx] = h; ol[idx] = l;
}

// ======================= fp16-split tensor-core GEMM =======================
#define WSTR 20
#define HGEMM_SMEM (2 * 4 * 128 * WSTR * 4)   // 81920 B

template<int TERMS>
__device__ __forceinline__ void hgemm_body(
    int N, int K, int m0, int n0,
    const __half* __restrict__ Ahi, const __half* __restrict__ Alo,
    const __half* __restrict__ Bhi,
    uint32_t* smw, float acc[2][4][4])
{
    uint32_t* buf[2] = { smw, smw + 4 * 128 * WSTR };
    const int tid = threadIdx.x;
    const int wid = tid >> 5, lane = tid & 31;
    const int warpM = (wid >> 2) * 32;
    const int warpN = (wid & 3) * 32;
    const int lr = lane >> 2, lc = lane & 3;

    const __half* Ap0 = Ahi + (size_t)m0 * K;
    const __half* Ap1 = (TERMS == 2) ? (Alo + (size_t)m0 * K) : nullptr;
    const __half* Bp  = Bhi + (size_t)n0 * K;

    const int r = tid >> 2;
    const int q = (tid & 3) * 4;

    auto stage = [&](int kc, int b) {
        uint32_t base = smem_u32(buf[b]);
        cp16(base + (uint32_t)((r) * WSTR + q) * 4u,
             Ap0 + (size_t)r * K + kc + q * 2);
        if (TERMS == 2)
            cp16(base + (uint32_t)((128 + r) * WSTR + q) * 4u,
                 Ap1 + (size_t)r * K + kc + q * 2);
        cp16(base + (uint32_t)((2 * 128 + r) * WSTR + q) * 4u,
             Bp + (size_t)r * K + kc + q * 2);
        CP_COMMIT();
    };

    uint32_t accl[2][4][2];
    #pragma unroll
    for (int i = 0; i < 2; i++)
        #pragma unroll
        for (int j = 0; j < 4; j++) {
            #pragma unroll
            for (int k = 0; k < 4; k++) acc[i][j][k] = 0.f;
            accl[i][j][0] = 0u; accl[i][j][1] = 0u;
        }

    stage(0, 0);

    const int nch = K >> 5;
    for (int i = 0; i < nch; i++) {
        CP_WAIT0();
        __syncthreads();
        if (i + 1 < nch) stage((i + 1) << 5, (i + 1) & 1);

        const uint32_t* Ah = buf[i & 1];
        const uint32_t* Al = Ah + 128 * WSTR;
        const uint32_t* Bh = Ah + 2 * 128 * WSTR;

        #pragma unroll
        for (int s = 0; s < 2; s++) {
            uint32_t ah[2][4], al[2][4], bhf[4][2];
            #pragma unroll
            for (int ma = 0; ma < 2; ma++) {
                int rw = (warpM + ma * 16 + lr) * WSTR + s * 8 + lc;
                ah[ma][0] = Ah[rw];
                ah[ma][1] = Ah[rw + 8 * WSTR];
                ah[ma][2] = Ah[rw + 4];
                ah[ma][3] = Ah[rw + 8 * WSTR + 4];
                if (TERMS == 2) {
                    al[ma][0] = Al[rw];
                    al[ma][1] = Al[rw + 8 * WSTR];
                    al[ma][2] = Al[rw + 4];
                    al[ma][3] = Al[rw + 8 * WSTR + 4];
                }
            }
            #pragma unroll
            for (int nb = 0; nb < 4; nb++) {
                int cw = (warpN + nb * 8 + lr) * WSTR + s * 8 + lc;
                bhf[nb][0] = Bh[cw]; bhf[nb][1] = Bh[cw + 4];
            }
            if (TERMS == 2) {
                #pragma unroll
                for (int nb = 0; nb < 4; nb++)
                    #pragma unroll
                    for (int ma = 0; ma < 2; ma++)
                        mma_h16(accl[ma][nb], al[ma][0], al[ma][1], al[ma][2], al[ma][3],
                                bhf[nb][0], bhf[nb][1]);
            }
            #pragma unroll
            for (int nb = 0; nb < 4; nb++)
                #pragma unroll
                for (int ma = 0; ma < 2; ma++)
                    mma_f16(acc[ma][nb], ah[ma][0], ah[ma][1], ah[ma][2], ah[ma][3],
                            bhf[nb][0], bhf[nb][1]);
        }
        __syncthreads();
    }

    if (TERMS == 2) {
        #pragma unroll
        for (int ma = 0; ma < 2; ma++)
            #pragma unroll
            for (int nb = 0; nb < 4; nb++) {
                float2 c01 = __half22float2(*(__half2*)&accl[ma][nb][0]);
                float2 c23 = __half22float2(*(__half2*)&accl[ma][nb][1]);
                acc[ma][nb][0] += c01.x;
                acc[ma][nb][1] += c01.y;
                acc[ma][nb][2] += c23.x;
                acc[ma][nb][3] += c23.y;
            }
    }
}

template<int TERMS>
__global__ __launch_bounds__(512)
void hgemm_f(int N, int K,
             const __half* __restrict__ Ahi, const __half* __restrict__ Alo,
             const __half* __restrict__ Bhi,
             float* __restrict__ C)
{
    extern __shared__ float smraw[];
    float acc[2][4][4];
    const int m0 = blockIdx.y * 128, n0 = blockIdx.x * 128;
    hgemm_body<TERMS>(N, K, m0, n0, Ahi, Alo, Bhi, (uint32_t*)smraw, acc);

    const int wid = threadIdx.x >> 5, lane = threadIdx.x & 31;
    const int warpM = (wid >> 2) * 32, warpN = (wid & 3) * 32;
    const int lr = lane >> 2, lc = lane & 3;
    #pragma unroll
    for (int ma = 0; ma < 2; ma++) {
        int row = m0 + warpM + ma * 16 + lr;
        #pragma unroll
        for (int nb = 0; nb < 4; nb++) {
            int col = n0 + warpN + nb * 8 + lc * 2;
            *(float2*)(C + (size_t)row * N + col)       = make_float2(acc[ma][nb][0], acc[ma][nb][1]);
            *(float2*)(C + (size_t)(row + 8) * N + col) = make_float2(acc[ma][nb][2], acc[ma][nb][3]);
        }
    }
}

// merged K=1024 launch: seg0 (32 tiles) ckv@UKV->kv, seg1 (32) cq@UQ->qc, seg2 (16) cq@QR->qr
__global__ __launch_bounds__(512)
void hgemm_multi(const __half* __restrict__ ckvh, const __half* __restrict__ ckvl,
                 const __half* __restrict__ cqh,  const __half* __restrict__ cql,
                 const __half* __restrict__ tUKVh,
                 const __half* __restrict__ tUQh,
                 const __half* __restrict__ tQRh,
                 __half* __restrict__ kvh,
                 __half* __restrict__ qch,
                 __half* __restrict__ qrh)
{
    extern __shared__ float smraw[];
    const int bx = blockIdx.x;
    const __half *Ahp, *Alp, *Bhp;
    __half *Chp;
    int N, nloc;
    if (bx < 32)      { Ahp = ckvh; Alp = ckvl; Bhp = tUKVh; Chp = kvh; N = 4096; nloc = bx; }
    else if (bx < 64) { Ahp = cqh;  Alp = cql;  Bhp = tUQh;  Chp = qch; N = 4096; nloc = bx - 32; }
    else              { Ahp = cqh;  Alp = cql;  Bhp = tQRh;  Chp = qrh; N = 2048; nloc = bx - 64; }

    float acc[2][4][4];
    const int m0 = blockIdx.y * 128, n0 = nloc * 128;
    hgemm_body<2>(N, 1024, m0, n0, Ahp, Alp, Bhp, (uint32_t*)smraw, acc);

    const int wid = threadIdx.x >> 5, lane = threadIdx.x & 31;
    const int warpM = (wid >> 2) * 32, warpN = (wid & 3) * 32;
    const int lr = lane >> 2, lc = lane & 3;
    #pragma unroll
    for (int ma = 0; ma < 2; ma++) {
        int row = m0 + warpM + ma * 16 + lr;
        #pragma unroll
        for (int nb = 0; nb < 4; nb++) {
            int col = n0 + warpN + nb * 8 + lc * 2;
            *(__half2*)(Chp + (size_t)row * N + col)       = __floats2half2_rn(acc[ma][nb][0], acc[ma][nb][1]);
            *(__half2*)(Chp + (size_t)(row + 8) * N + col) = __floats2half2_rn(acc[ma][nb][2], acc[ma][nb][3]);
        }
    }
}

// ======================= fused dual RMS norm -> fp16 split planes =======================
// grid (BL, 2): y=0 -> ckv (cols 0..1023, kv_w), y=1 -> cq (cols 1024..2047, q_w)
__global__ void rms2_h(const float* __restrict__ tmp,
                       const float* __restrict__ kv_w, const float* __restrict__ q_w,
                       __half* __restrict__ ckvh, __half* __restrict__ ckvl,
                       __half* __restrict__ cqh,  __half* __restrict__ cql)
{
    int row = blockIdx.x;
    int half = blockIdx.y;
    const float* ir = tmp + (size_t)row * NX + half * 1024;
    const float* w  = half ? q_w : kv_w;
    __half* oh = half ? cqh : ckvh;
    __half* ol = half ? cql : ckvl;

    float s = 0.f;
    for (int i = threadIdx.x; i < DCc; i += 256) { float v = ir[i]; s += v * v; }
    __shared__ float red[256];
    red[threadIdx.x] = s;
    __syncthreads();
    for (int st = 128; st > 0; st >>= 1) {
        if (threadIdx.x < st) red[threadIdx.x] += red[threadIdx.x + st];
        __syncthreads();
    }
    float rr = rsqrtf(red[0] / (float)DCc + 1e-6f);
    for (int i = threadIdx.x; i < DCc; i += 256) {
        float v = ir[i] * rr * w[i];
        __half h, l; split16(v, h, l);
        oh[(size_t)row * DCc + i] = h;
        ol[(size_t)row * DCc + i] = l;
    }
}

// ======================= fused epilogue: lambda sigmoid + RoPE kr (per row) ============
__global__ void epi_row(const float* __restrict__ tmp, const float* __restrict__ bl,
                        float* __restrict__ lam, __half* __restrict__ krh)
{
    int row = blockIdx.x;
    int t = threadIdx.x;   // 64
    const float* base = tmp + (size_t)row * NX + 2048;
    if (t < 32) {
        int j = t;
        int l = row & (Lseq - 1);
        float inv = powf(10000.f, -(float)(2 * j) / 64.f);
        float ang = (float)l * inv;
        float c = cosf(ang), s = sinf(ang);
        float x1 = base[j], x2 = base[j + 32];
        size_t o = (size_t)row * 64;
        krh[o + j]      = __float2half_rn(x1 * c - x2 * s);
        krh[o + j + 32] = __float2half_rn(x2 * c + x1 * s);
    } else if (t < 48) {
        int n = t - 32;
        float z = base[64 + n] + bl[n];
        lam[(size_t)row * 16 + n] = 1.f / (1.f + expf(-z));
    }
}

// ======================= RoPE qr (in-place on hi plane) =======================
__global__ void rope_qp(__half* __restrict__ ph)
{
    int idx = blockIdx.x * 256 + threadIdx.x;   // BL*32*32
    int j = idx & 31;
    int h = (idx >> 5) & 31;
    int row = idx >> 10;
    int l = row & (Lseq - 1);
    float inv = powf(10000.f, -(float)(2 * j) / 64.f);
    float ang = (float)l * inv;
    float c = cosf(ang), s = sinf(ang);
    size_t o = (size_t)row * 2048 + h * 64;
    float x1 = __half2float(ph[o + j]);
    float x2 = __half2float(ph[o + j + 32]);
    ph[o + j]      = __float2half_rn(x1 * c - x2 * s);
    ph[o + j + 32] = __float2half_rn(x2 * c + x1 * s);
}

// ======================= fused differential flash attention (1-term fp16) =====
// One CTA handles both p=0 and p=1 of head n over the same K/V; epilogue computes
// pre = attn0 - lam*attn1 in f32 and writes fp16 hi plane directly.
// smem words: qs0 6400 | qs1 6400 | ks 3200 | vs 2176 | ps 1280 = 19456 -> 77824 B
#define FLASH_SMEM (19456 * 4)
__global__ __launch_bounds__(128)
void flash_h2(const __half* __restrict__ qch,
              const __half* __restrict__ qrh,
              const __half* __restrict__ kvh,
              const __half* __restrict__ krh,
              const float* __restrict__ lam,
              __half* __restrict__ preh)
{
    extern __shared__ uint32_t smw[];
    uint32_t* qs[2] = { smw, smw + 6400 };
    uint32_t* ks = smw + 12800;
    uint32_t* vs = smw + 16000;
    uint32_t* ps = smw + 18176;

    const int Q0 = (gridDim.x - 1 - blockIdx.x) * 64;   // longest work first
    const int hn = blockIdx.y;
    const int b = blockIdx.z;
    const int tid = threadIdx.x;
    const int lane = tid & 31, w = tid >> 5;
    const int lr = lane >> 2, lc = lane & 3;

    const size_t tq = (size_t)(b * Lseq + Q0);

    // ---- stage both Q planes (head2 = 2n, 2n+1) ----
    {
        #pragma unroll
        for (int p = 0; p < 2; p++) {
            const __half* qcp = qch + tq * 4096 + (2 * hn + p) * 128;
            const __half* qrp = qrh + tq * 2048 + (2 * hn + p) * 64;
            uint32_t qb = smem_u32(qs[p]);
            #pragma unroll
            for (int i = 0; i < 8; i++) {
                int s2 = tid + i * 128;
                int r = s2 >> 4, c = s2 & 15;
                cp16(qb + (uint32_t)(r * 100 + c * 4) * 4u, qcp + (size_t)r * 4096 + c * 8);
            }
            #pragma unroll
            for (int i = 0; i < 4; i++) {
                int s2 = tid + i * 128;
                int r = s2 >> 3, c = s2 & 7;
                cp16(qb + (uint32_t)(r * 100 + 64 + c * 4) * 4u, qrp + (size_t)r * 2048 + c * 8);
            }
        }
        CP_COMMIT();
    }

    float o0[16][4], o1[16][4];
    #pragma unroll
    for (int i = 0; i < 16; i++) {
        o0[i][0] = o0[i][1] = o0[i][2] = o0[i][3] = 0.f;
        o1[i][0] = o1[i][1] = o1[i][2] = o1[i][3] = 0.f;
    }
    // softmax state: [p][row-half]
    float mm[2][2] = {{-INFINITY, -INFINITY}, {-INFINITY, -INFINITY}};
    float ll[2][2] = {{0.f, 0.f}, {0.f, 0.f}};

    const int row0g = Q0 + 16 * w + lr;
    const int row1g = row0g + 8;
    const int prow0 = (16 * w + lr) * 20;
    const int arow0 = (16 * w + lr) * 100;

    const int ntile = (Q0 + 64) >> 5;
    for (int t = 0; t < ntile; t++) {
        const int k0 = t << 5;
        __syncthreads();
        // ---- stage K (kc|kr) and V once for both p ----
        {
            const size_t tk = (size_t)(b * Lseq + k0);
            const __half* kcp = kvh + tk * 4096 + hn * 128;
            const __half* vp  = kvh + tk * 4096 + 2048 + hn * 128;
            const __half* krp = krh + tk * 64;
            uint32_t kb = smem_u32(ks);
            uint32_t vb = smem_u32(vs);
            #pragma unroll
            for (int i = 0; i < 4; i++) {
                int s2 = tid + i * 128;
                int r = s2 >> 4, c = s2 & 15;
                cp16(kb + (uint32_t)(r * 100 + c * 4) * 4u, kcp + (size_t)r * 4096 + c * 8);
                cp16(vb + (uint32_t)(r * 68 + c * 4) * 4u,  vp  + (size_t)r * 4096 + c * 8);
            }
            #pragma unroll
            for (int i = 0; i < 2; i++) {
                int s2 = tid + i * 128;
                int r = s2 >> 3, c = s2 & 7;
                cp16(kb + (uint32_t)(r * 100 + 64 + c * 4) * 4u, krp + (size_t)r * 64 + c * 8);
            }
            CP_COMMIT();
            CP_WAIT0();
            __syncthreads();
        }

        #pragma unroll
        for (int p = 0; p < 2; p++) {
            float (*o)[4] = p ? o1 : o0;
            const uint32_t* qsp = qs[p];

            // ---- S = Q @ K^T ----
            float s4[4][4];
            #pragma unroll
            for (int nt = 0; nt < 4; nt++) { s4[nt][0] = s4[nt][1] = s4[nt][2] = s4[nt][3] = 0.f; }

            #pragma unroll 4
            for (int s = 0; s < 12; s++) {
                const int ab = arow0 + s * 8 + lc;
                uint32_t ah0 = qsp[ab],     ah1 = qsp[ab + 800];
                uint32_t ah2 = qsp[ab + 4], ah3 = qsp[ab + 804];
                #pragma unroll
                for (int nt = 0; nt < 4; nt++) {
                    const int cb = (nt * 8 + lr) * 100 + s * 8 + lc;
                    mma_f16(s4[nt], ah0, ah1, ah2, ah3, ks[cb], ks[cb + 4]);
                }
            }

            // ---- mask + scale + online softmax ----
            float tmax0 = -INFINITY, tmax1 = -INFINITY;
            #pragma unroll
            for (int nt = 0; nt < 4; nt++) {
                const int colg = k0 + nt * 8 + 2 * lc;
                s4[nt][0] = (colg     <= row0g) ? s4[nt][0] * ATTN_SCALE : -INFINITY;
                s4[nt][1] = (colg + 1 <= row0g) ? s4[nt][1] * ATTN_SCALE : -INFINITY;
                s4[nt][2] = (colg     <= row1g) ? s4[nt][2] * ATTN_SCALE : -INFINITY;
                s4[nt][3] = (colg + 1 <= row1g) ? s4[nt][3] * ATTN_SCALE : -INFINITY;
                tmax0 = fmaxf(tmax0, fmaxf(s4[nt][0], s4[nt][1]));
                tmax1 = fmaxf(tmax1, fmaxf(s4[nt][2], s4[nt][3]));
            }
            tmax0 = fmaxf(tmax0, __shfl_xor_sync(0xffffffffu, tmax0, 1));
            tmax0 = fmaxf(tmax0, __shfl_xor_sync(0xffffffffu, tmax0, 2));
            tmax1 = fmaxf(tmax1, __shfl_xor_sync(0xffffffffu, tmax1, 1));
            tmax1 = fmaxf(tmax1, __shfl_xor_sync(0xffffffffu, tmax1, 2));

            const float mn0 = fmaxf(mm[p][0], tmax0), mn1 = fmaxf(mm[p][1], tmax1);
            const float scl0 = expf(mm[p][0] - mn0);
            const float scl1 = expf(mm[p][1] - mn1);

            float p4[4][4];
            float pr0 = 0.f, pr1 = 0.f;
            #pragma unroll
            for (int nt = 0; nt < 4; nt++) {
                p4[nt][0] = expf(s4[nt][0] - mn0);
                p4[nt][1] = expf(s4[nt][1] - mn0);
                p4[nt][2] = expf(s4[nt][2] - mn1);
                p4[nt][3] = expf(s4[nt][3] - mn1);
                pr0 += p4[nt][0] + p4[nt][1];
                pr1 += p4[nt][2] + p4[nt][3];
            }
            pr0 += __shfl_xor_sync(0xffffffffu, pr0, 1);
            pr0 += __shfl_xor_sync(0xffffffffu, pr0, 2);
            pr1 += __shfl_xor_sync(0xffffffffu, pr1, 1);
            pr1 += __shfl_xor_sync(0xffffffffu, pr1, 2);

            ll[p][0] = ll[p][0] * scl0 + pr0;
            ll[p][1] = ll[p][1] * scl1 + pr1;
            mm[p][0] = mn0; mm[p][1] = mn1;

            #pragma unroll
            for (int i = 0; i < 16; i++) {
                o[i][0] *= scl0; o[i][1] *= scl0;
                o[i][2] *= scl1; o[i][3] *= scl1;
            }

            // ---- P -> fp16 (per-warp private rows) ----
            __syncwarp();
            #pragma unroll
            for (int nt = 0; nt < 4; nt++) {
                ((__half2*)ps)[prow0 + nt * 4 + lc]       = __floats2half2_rn(p4[nt][0], p4[nt][1]);
                ((__half2*)ps)[prow0 + 160 + nt * 4 + lc] = __floats2half2_rn(p4[nt][2], p4[nt][3]);
            }
            __syncwarp();

            // ---- O += P @ V ----
            const uint16_t* vhp = (const uint16_t*)vs;
            #pragma unroll
            for (int s = 0; s < 2; s++) {
                const int pb = prow0 + s * 8 + lc;
                uint32_t ah0 = ps[pb],     ah1 = ps[pb + 160];
                uint32_t ah2 = ps[pb + 4], ah3 = ps[pb + 164];
                const int kb = s * 16 + 2 * lc;
                #pragma unroll
                for (int nt2 = 0; nt2 < 16; nt2++) {
                    const int d = nt2 * 8 + lr;
                    uint32_t bh0 = (uint32_t)vhp[kb * 136 + d]       | ((uint32_t)vhp[(kb + 1) * 136 + d] << 16);
                    uint32_t bh1 = (uint32_t)vhp[(kb + 8) * 136 + d] | ((uint32_t)vhp[(kb + 9) * 136 + d] << 16);
                    mma_f16(o[nt2], ah0, ah1, ah2, ah3, bh0, bh1);
                }
            }
        }
    }

    // ---- epilogue: pre = attn0 - lam*attn1 ----
    const float i00 = 1.f / ll[0][0], i01 = 1.f / ll[0][1];
    const float i10 = 1.f / ll[1][0], i11 = 1.f / ll[1][1];
    const float lamr0 = lam[(size_t)(b * Lseq + row0g) * 16 + hn];
    const float lamr1 = lam[(size_t)(b * Lseq + row1g) * 16 + hn];
    __half* op0 = preh + (size_t)(b * Lseq + row0g) * 2048 + hn * 128;
    __half* op1 = preh + (size_t)(b * Lseq + row1g) * 2048 + hn * 128;
    #pragma unroll
    for (int nt2 = 0; nt2 < 16; nt2++) {
        float v00 = o0[nt2][0] * i00 - lamr0 * (o1[nt2][0] * i10);
        float v01 = o0[nt2][1] * i00 - lamr0 * (o1[nt2][1] * i10);
        float v10 = o0[nt2][2] * i01 - lamr1 * (o1[nt2][2] * i11);
        float v11 = o0[nt2][3] * i01 - lamr1 * (o1[nt2][3] * i11);
        *(__half2*)(op0 + nt2 * 8 + 2 * lc) = __floats2half2_rn(v00, v01);
        *(__half2*)(op1 + nt2 * 8 + 2 * lc) = __floats2half2_rn(v10, v11);
    }
}

// ======================= launch =======================
extern "C" void kernel_launch(void* const* d_in, const int* in_sizes, int n_in,
                              void* d_out, int out_size)
{
    const float* x     = (const float*)d_in[0];
    const float* W_DKV = (const float*)d_in[1];
    const float* kv_w  = (const float*)d_in[2];
    const float* W_UK  = (const float*)d_in[3];
    const float* W_UV  = (const float*)d_in[4];
    const float* W_DQ  = (const float*)d_in[5];
    const float* q_w   = (const float*)d_in[6];
    const float* W_UQ  = (const float*)d_in[7];
    const float* W_QR  = (const float*)d_in[8];
    const float* W_KR  = (const float*)d_in[9];
    const float* W_lw  = (const float*)d_in[10];
    const float* W_lb  = (const float*)d_in[11];
    const float* W_out = (const float*)d_in[12];
    float* out = (float*)d_out;

    float *tmp, *lam;
    __half *xh, *xl, *ckvh, *ckvl, *cqh, *cql, *preh;
    __half *qchp, *qrhp, *krhp, *kvh;
    __half *tXh, *tXl, *tUKVh, *tUQh, *tQRh, *tOUTh;
    cudaGetSymbolAddress((void**)&tmp,  g_tmp);
    cudaGetSymbolAddress((void**)&lam,  g_lam);
    cudaGetSymbolAddress((void**)&xh,   g_xh);
    cudaGetSymbolAddress((void**)&xl,   g_xl);
    cudaGetSymbolAddress((void**)&ckvh, g_ckvh);
    cudaGetSymbolAddress((void**)&ckvl, g_ckvl);
    cudaGetSymbolAddress((void**)&cqh,  g_cqh);
    cudaGetSymbolAddress((void**)&cql,  g_cql);
    cudaGetSymbolAddress((void**)&preh, g_preh);
    cudaGetSymbolAddress((void**)&qchp, g_qch);
    cudaGetSymbolAddress((void**)&qrhp, g_qrh);
    cudaGetSymbolAddress((void**)&krhp, g_krh);
    cudaGetSymbolAddress((void**)&kvh,  g_kvh);
    cudaGetSymbolAddress((void**)&tXh,  g_tXh);
    cudaGetSymbolAddress((void**)&tXl,  g_tXl);
    cudaGetSymbolAddress((void**)&tUKVh, g_tUKVh);
    cudaGetSymbolAddress((void**)&tUQh,  g_tUQh);
    cudaGetSymbolAddress((void**)&tQRh,  g_tQRh);
    cudaGetSymbolAddress((void**)&tOUTh, g_tOUTh);

    cudaFuncSetAttribute(hgemm_f<2>,  cudaFuncAttributeMaxDynamicSharedMemorySize, HGEMM_SMEM);
    cudaFuncSetAttribute(hgemm_f<1>,  cudaFuncAttributeMaxDynamicSharedMemorySize, HGEMM_SMEM);
    cudaFuncSetAttribute(hgemm_multi, cudaFuncAttributeMaxDynamicSharedMemorySize, HGEMM_SMEM);
    cudaFuncSetAttribute(flash_h2,    cudaFuncAttributeMaxDynamicSharedMemorySize, FLASH_SMEM);

    dim3 tb(32, 8);
    // fused tX planes: rows [DKV 0..1023 | DQ 1024..2047 | KR 2048..2111 | lw 2112..2127 | pad]
    transpose32h<<<dim3(DCc/32, Dd/32), tb>>>(W_DKV, tXh,              tXl,              Dd, DCc);
    transpose32h<<<dim3(DCc/32, Dd/32), tb>>>(W_DQ,  tXh + 1024 * Dd,  tXl + 1024 * Dd,  Dd, DCc);
    transpose32h<<<dim3(DHRr/32, Dd/32), tb>>>(W_KR, tXh + 2048 * Dd,  tXl + 2048 * Dd,  Dd, DHRr);
    lwT_kernel<<<(Dd * 16) / 256, 256>>>(W_lw, tXh, tXl);
    // up-proj / out-proj weights: hi plane only
    transpose32h<<<dim3((NHh*DHh)/32, DCc/32), tb>>>(W_UK, tUKVh,              nullptr, DCc, NHh*DHh);
    transpose32h<<<dim3((NHh*DHh)/32, DCc/32), tb>>>(W_UV, tUKVh + 2048 * DCc, nullptr, DCc, NHh*DHh);
    transpose32h<<<dim3((2*NHh*DHh)/32, DCc/32), tb>>>(W_UQ, tUQh, nullptr, DCc, 2*NHh*DHh);
    transpose32h<<<dim3((2*NHh*DHRr)/32, DCc/32), tb>>>(W_QR, tQRh, nullptr, DCc, 2*NHh*DHRr);
    transpose32h<<<dim3(Dd/32, Dd/32), tb>>>(W_out, tOUTh, nullptr, Dd, Dd);
    split_kernel<<<(BL * Dd) / 256, 256>>>(x, xh, xl);

    // fused down-projection + kr + lambda-pre (2-term split): tmp[row][NX]
    hgemm_f<2><<<dim3(NX/128, BL/128), 512, HGEMM_SMEM>>>(NX, Dd, xh, xl, tXh, tmp);
    rms2_h<<<dim3(BL, 2), 256>>>(tmp, kv_w, q_w, ckvh, ckvl, cqh, cql);
    epi_row<<<BL, 64>>>(tmp, W_lb, lam, krhp);

    // merged up-projections (UKV + UQ + QR), K=1024, 2-term split, hi-only outputs
    hgemm_multi<<<dim3(80, BL/128), 512, HGEMM_SMEM>>>(
        ckvh, ckvl, cqh, cql,
        tUKVh, tUQh, tQRh,
        kvh, qchp, qrhp);

    // RoPE on qr hi plane (in-place)
    rope_qp<<<(BL * 1024) / 256, 256>>>(qrhp);

    // fused differential attention (both p in one CTA), writes pre directly
    flash_h2<<<dim3(Lseq / 64, NHh, BB), 128, FLASH_SMEM>>>(
        qchp, qrhp, kvh, krhp, lam, preh);

    // output projection (1-term)
    hgemm_f<1><<<dim3(Dd/128, BL/128), 512, HGEMM_SMEM>>>(Dd, Dd, preh, nullptr, tOUTh, out);
}